// round 8
// baseline (speedup 1.0000x reference)
#include <cuda_runtime.h>
#include <cstdint>

// ---------------- problem constants ----------------
#define NE   8
#define NT   16384
#define NIN  2048
#define NOUT 2048

// ---------------- GEMM tiling ----------------
#define BM 128
#define BN 256
#define BK 32
#define KITERS (NIN / BK)              // 64
#define NTHREADS 320                   // 8 compute warps + 2 producer warps

// ---------------- smem layout ----------------
// raw ring (2 stages): fp32 tiles, rows padded to 36 floats (144B, 16B-aligned)
#define RAWSTRIDE 36
#define RAW_A_BYTES (BM * RAWSTRIDE * 4)    // 18432
#define RAW_B_BYTES (BN * RAWSTRIDE * 4)    // 36864
#define RAW_STAGE_BYTES (RAW_A_BYTES + RAW_B_BYTES)   // 55296
// fragment ring (2 stages): R4-identical fragment-native tf32 layout
#define FRAG_A_BYTES (BM * BK * 4)          // 16384
#define FRAG_B_BYTES (BN * BK * 4)          // 32768
#define FRAG_STAGE_BYTES (FRAG_A_BYTES + FRAG_B_BYTES) // 49152
#define SMEM_CTRL 1024
#define RAW_OFF  SMEM_CTRL
#define FRAG_OFF (SMEM_CTRL + 2 * RAW_STAGE_BYTES)     // 111616
#define SMEM_TOTAL (FRAG_OFF + 2 * FRAG_STAGE_BYTES)   // 209920

// ---------------- helpers (all plain-sm_103-legal) ----------------
__device__ __forceinline__ uint32_t smem_u32(const void* p) {
    uint32_t a;
    asm("{ .reg .u64 t; cvta.to.shared.u64 t, %1; cvt.u32.u64 %0, t; }" : "=r"(a) : "l"(p));
    return a;
}

__device__ __forceinline__ float tf32r(float f) {   // round-to-nearest tf32
    uint32_t r;
    asm("cvt.rna.tf32.f32 %0, %1;" : "=r"(r) : "f"(f));
    return __uint_as_float(r);
}

__device__ __forceinline__ void cp16(uint32_t smem_dst, const float* gsrc) {
    asm volatile("cp.async.cg.shared.global [%0], [%1], 16;" :: "r"(smem_dst), "l"(gsrc));
}
#define CP_COMMIT() asm volatile("cp.async.commit_group;" ::: "memory")
#define CP_WAIT1()  asm volatile("cp.async.wait_group 1;" ::: "memory")

#define MBAR_INIT(a, c) \
    asm volatile("mbarrier.init.shared.b64 [%0], %1;" :: "r"(a), "r"(c) : "memory")
#define MBAR_ARRIVE(a) \
    asm volatile("mbarrier.arrive.shared.b64 _, [%0];" :: "r"(a) : "memory")

#define MBAR_WAIT(addr, ph) do {                                                   \
    asm volatile("{\n\t.reg .pred P1;\n\t"                                         \
        "WL%=:\n\t"                                                                \
        "mbarrier.try_wait.parity.acquire.cta.shared::cta.b64 P1, [%0], %1, 0x989680;\n\t" \
        "@P1 bra.uni WD%=;\n\t"                                                    \
        "bra.uni WL%=;\n\t"                                                        \
        "WD%=:\n\t}"                                                               \
        :: "r"(addr), "r"(ph) : "memory");                                         \
} while (0)

#define PROD_BAR() asm volatile("bar.sync 1, 64;" ::: "memory")

__device__ __forceinline__ void lds128(uint32_t* r, uint32_t addr) {
    asm volatile("ld.shared.v4.b32 {%0,%1,%2,%3}, [%4];"
                 : "=r"(r[0]), "=r"(r[1]), "=r"(r[2]), "=r"(r[3]) : "r"(addr));
}
__device__ __forceinline__ void lds64(uint32_t* r, uint32_t addr) {
    asm volatile("ld.shared.v2.b32 {%0,%1}, [%2];"
                 : "=r"(r[0]), "=r"(r[1]) : "r"(addr));
}

__device__ __forceinline__ void mma_tf32(float* d, const uint32_t* a, const uint32_t* b) {
    asm volatile(
        "mma.sync.aligned.m16n8k8.row.col.f32.tf32.tf32.f32 "
        "{%0,%1,%2,%3}, {%4,%5,%6,%7}, {%8,%9}, {%0,%1,%2,%3};"
        : "+f"(d[0]), "+f"(d[1]), "+f"(d[2]), "+f"(d[3])
        : "r"(a[0]), "r"(a[1]), "r"(a[2]), "r"(a[3]), "r"(b[0]), "r"(b[1]));
}

// ---------------- fused grouped GEMM: producer-convert pipeline -----------------
__global__ void __launch_bounds__(NTHREADS, 1) gemm_kernel(
        const float* __restrict__ x,
        const float* __restrict__ w,
        const float* __restrict__ bias,
        const int*   __restrict__ tpe,
        float*       __restrict__ out) {
    extern __shared__ __align__(16) char smem[];

    const int e  = blockIdx.z;
    const int mt = blockIdx.y;
    const int nt = blockIdx.x;

    int start = 0, mycnt = 0;
    #pragma unroll
    for (int i = 0; i < NE; i++) {
        int cc = __ldg(tpe + i);
        if (i < e) start += cc;
        if (i == e) mycnt = cc;
    }
    if (mt * BM >= mycnt) return;

    const int tid = threadIdx.x;
    const int m0  = start + mt * BM;            // global token row of tile
    const int nr0 = e * NOUT + nt * BN;         // global w row of tile

    const uint32_t sb     = smem_u32(smem);
    const uint32_t fullb  = sb;                 // 2 x 8B
    const uint32_t emptyb = sb + 64;            // 2 x 8B

    if (tid == 0) {
        #pragma unroll
        for (int s = 0; s < 2; s++) {
            MBAR_INIT(fullb + s * 8, 64);       // 64 producer threads signal
            MBAR_INIT(emptyb + s * 8, 256);     // 256 compute threads signal
        }
    }
    __syncthreads();

    if (tid >= 256) {
        // ============ producer warps (2 warps, 64 threads): load + convert ======
        const int ptid = tid - 256;             // 0..63
        const float* xA = x + (size_t)m0 * NIN;
        const float* wB = w + (size_t)nr0 * NIN;

        // raw-stage fill: 48 cp.async(16B) per thread, rows padded to 144B
        auto fill_raw = [&](int k, int s) {
            const uint32_t rA = sb + RAW_OFF + s * RAW_STAGE_BYTES;
            const uint32_t rB = rA + RAW_A_BYTES;
            const float* As = xA + k * BK;
            const float* Bs = wB + k * BK;
            #pragma unroll
            for (int i = 0; i < 16; i++) {      // A: 128 rows x 8 chunks of 16B
                int idx = ptid + i * 64;
                int row = idx >> 3, c = idx & 7;
                cp16(rA + row * (RAWSTRIDE * 4) + c * 16, As + (size_t)row * NIN + c * 4);
            }
            #pragma unroll
            for (int i = 0; i < 32; i++) {      // B: 256 rows x 8 chunks of 16B
                int idx = ptid + i * 64;
                int row = idx >> 3, c = idx & 7;
                cp16(rB + row * (RAWSTRIDE * 4) + c * 16, Bs + (size_t)row * NIN + c * 4);
            }
            CP_COMMIT();
        };

        fill_raw(0, 0);
        fill_raw(1, 1);

        #pragma unroll 1
        for (int k = 0; k < KITERS; k++) {
            const int s = k & 1;
            CP_WAIT1();                          // raw[k] landed (own chunks)
            PROD_BAR();                          // all producers' chunks visible
            if (k >= 2) MBAR_WAIT(emptyb + s * 8, ((k >> 1) - 1) & 1);

            const float* rawA = (const float*)(smem + RAW_OFF + s * RAW_STAGE_BYTES);
            const float* rawB = rawA + BM * RAWSTRIDE;
            float* fragA = (float*)(smem + FRAG_OFF + s * FRAG_STAGE_BYTES);
            float* fragB = fragA + BM * BK;

            // ---- convert A: 1024 float4 chunks, conflict-free gathers ----
            #pragma unroll
            for (int i = 0; i < 16; i++) {
                const int idx    = ptid + i * 64;
                const int kcu    = idx >> 8;
                const int rem    = idx & 255;
                const int mtile  = rem >> 5;
                const int within = rem & 31;
                const int lrg    = within >> 2;
                const int q      = within & 3;
                const int row0   = mtile * 16 + lrg;
                const int c      = kcu * 8 + q;
                float4 o;
                o.x = tf32r(rawA[row0 * RAWSTRIDE + c]);
                o.y = tf32r(rawA[(row0 + 8) * RAWSTRIDE + c]);
                o.z = tf32r(rawA[row0 * RAWSTRIDE + c + 4]);
                o.w = tf32r(rawA[(row0 + 8) * RAWSTRIDE + c + 4]);
                *(float4*)(fragA + idx * 4) = o;
            }
            // ---- convert B: 2048 float4 chunks ----
            #pragma unroll
            for (int i = 0; i < 32; i++) {
                const int idx   = ptid + i * 64;
                const int kcl   = idx >> 9;
                const int rem   = idx & 511;
                const int ntile = rem >> 4;
                const int d     = rem & 15;
                const int ln    = d >> 1;
                const int bsel  = d & 1;
                const int row   = ntile * 8 + ln;
                const int c0    = kcl * 8 + 2 * bsel;
                float4 o;
                o.x = tf32r(rawB[row * RAWSTRIDE + c0]);
                o.y = tf32r(rawB[row * RAWSTRIDE + c0 + 4]);
                o.z = tf32r(rawB[row * RAWSTRIDE + c0 + 1]);
                o.w = tf32r(rawB[row * RAWSTRIDE + c0 + 5]);
                *(float4*)(fragB + idx * 4) = o;
            }

            MBAR_ARRIVE(fullb + s * 8);          // release: orders prior STS
            PROD_BAR();                          // raw[s] reads done by all
            if (k + 2 < KITERS) fill_raw(k + 2, s);
            else CP_COMMIT();                    // keep group count uniform
        }
    } else {
        // ============ compute warps (8 warps, 256 threads): R4-identical ========
        const int lane = tid & 31;
        const int wid  = tid >> 5;
        const int wm   = wid & 1;                // 2 warp rows (64 rows each)
        const int wn   = wid >> 1;               // 4 warp cols (64 cols each)

        float acc[4][8][4];
        #pragma unroll
        for (int i = 0; i < 4; i++)
            #pragma unroll
            for (int j = 0; j < 8; j++)
                #pragma unroll
                for (int q = 0; q < 4; q++) acc[i][j][q] = 0.0f;

        #pragma unroll 1
        for (int k = 0; k < KITERS; k++) {
            const int s = k & 1;
            MBAR_WAIT(fullb + s * 8, (k >> 1) & 1);
            const uint32_t aBase = sb + FRAG_OFF + s * FRAG_STAGE_BYTES;
            const uint32_t bBase = aBase + FRAG_A_BYTES;
            #pragma unroll
            for (int kcl = 0; kcl < 4; kcl++) {
                uint32_t af[4][4], bf[8][2];
                #pragma unroll
                for (int i = 0; i < 4; i++)
                    lds128(af[i], aBase + ((kcl * 8 + wm * 4 + i) * 128 + lane * 4) * 4);
                #pragma unroll
                for (int j = 0; j < 8; j++)
                    lds64(bf[j], bBase + ((kcl * 32 + wn * 8 + j) * 64 + lane * 2) * 4);
                #pragma unroll
                for (int i = 0; i < 4; i++)
                    #pragma unroll
                    for (int j = 0; j < 8; j++)
                        mma_tf32(acc[i][j], af[i], bf[j]);
            }
            MBAR_ARRIVE(emptyb + s * 8);         // release: orders prior LDS reads
        }

        // ---- epilogue: bias add + fp32 store ----
        const int ncol0 = nt * BN + wn * 64;
        const float* bptr = bias + (size_t)e * NOUT + ncol0;
        #pragma unroll
        for (int j = 0; j < 8; j++) {
            const int cb = j * 8 + (lane & 3) * 2;
            const float bx = __ldg(bptr + cb);
            const float by = __ldg(bptr + cb + 1);
            #pragma unroll
            for (int i = 0; i < 4; i++) {
                const int r0 = wm * 64 + i * 16 + (lane >> 2);
                if (mt * BM + r0 < mycnt) {
                    float2 v = make_float2(acc[i][j][0] + bx, acc[i][j][1] + by);
                    *(float2*)(out + (size_t)(m0 + r0) * NOUT + ncol0 + cb) = v;
                }
                if (mt * BM + r0 + 8 < mycnt) {
                    float2 v = make_float2(acc[i][j][2] + bx, acc[i][j][3] + by);
                    *(float2*)(out + (size_t)(m0 + r0 + 8) * NOUT + ncol0 + cb) = v;
                }
            }
        }
    }
}

// ---------------- host launch ----------------
extern "C" void kernel_launch(void* const* d_in, const int* in_sizes, int n_in,
                              void* d_out, int out_size) {
    const float* x    = (const float*)d_in[0];
    const float* w    = (const float*)d_in[1];
    const float* bias = (const float*)d_in[2];
    const int*   tpe  = (const int*)d_in[3];
    float*       out  = (float*)d_out;

    cudaFuncSetAttribute(gemm_kernel,
                         cudaFuncAttributeMaxDynamicSharedMemorySize, SMEM_TOTAL);
    dim3 grid(NOUT / BN, NT / BM, NE);          // (8, 128, 8), ragged exit
    gemm_kernel<<<grid, NTHREADS, SMEM_TOTAL>>>(x, w, bias, tpe, out);
}

// round 9
// speedup vs baseline: 2.0663x; 2.0663x over previous
#include <cuda_runtime.h>
#include <cstdint>

// ---------------- problem constants ----------------
#define NE   8
#define NT   16384
#define NIN  2048
#define NOUT 2048

// ---------------- GEMM tiling (R4-identical) ----------------
#define BM 128
#define BN 256
#define BK 32
#define KITERS (NIN / BK)            // 64
#define STAGES 4
#define A_STAGE_BYTES (BM * BK * 4)  // 16384
#define B_STAGE_BYTES (BN * BK * 4)  // 32768
#define STAGE_BYTES (A_STAGE_BYTES + B_STAGE_BYTES)   // 49152
#define SMEM_CTRL 1024
#define SMEM_TOTAL (SMEM_CTRL + STAGES * STAGE_BYTES) // 197632
#define NTHREADS 320                 // 8 compute warps + 2 producer warps
#define MAXTILES 136                 // NT/BM + NE worst-case active m-tiles

// ---------------- scratch: tf32-rounded, fragment-native layouts ----------------
__device__ float g_A[(size_t)NT * NIN];
__device__ float g_W[(size_t)NE * NOUT * NIN];

// ---------------- helpers (all plain-sm_103-legal) ----------------
__device__ __forceinline__ uint32_t smem_u32(const void* p) {
    uint32_t a;
    asm("{ .reg .u64 t; cvta.to.shared.u64 t, %1; cvt.u32.u64 %0, t; }" : "=r"(a) : "l"(p));
    return a;
}

__device__ __forceinline__ float tf32r(float f) {   // round-to-nearest tf32
    uint32_t r;
    asm("cvt.rna.tf32.f32 %0, %1;" : "=r"(r) : "f"(f));
    return __uint_as_float(r);
}

__device__ __forceinline__ void cp16(uint32_t smem_dst, const float* gsrc) {
    asm volatile("cp.async.cg.shared.global [%0], [%1], 16;" :: "r"(smem_dst), "l"(gsrc));
}

#define MBAR_INIT(a, c) \
    asm volatile("mbarrier.init.shared.b64 [%0], %1;" :: "r"(a), "r"(c) : "memory")
#define MBAR_ARRIVE(a) \
    asm volatile("mbarrier.arrive.shared.b64 _, [%0];" :: "r"(a) : "memory")
#define CP_MBAR_ARRIVE(a) \
    asm volatile("cp.async.mbarrier.arrive.noinc.shared.b64 [%0];" :: "r"(a) : "memory")

#define MBAR_WAIT(addr, ph) do {                                                   \
    asm volatile("{\n\t.reg .pred P1;\n\t"                                         \
        "WL%=:\n\t"                                                                \
        "mbarrier.try_wait.parity.acquire.cta.shared::cta.b64 P1, [%0], %1, 0x989680;\n\t" \
        "@P1 bra.uni WD%=;\n\t"                                                    \
        "bra.uni WL%=;\n\t"                                                        \
        "WD%=:\n\t}"                                                               \
        :: "r"(addr), "r"(ph) : "memory");                                         \
} while (0)

__device__ __forceinline__ void lds128(uint32_t* r, uint32_t addr) {
    asm volatile("ld.shared.v4.b32 {%0,%1,%2,%3}, [%4];"
                 : "=r"(r[0]), "=r"(r[1]), "=r"(r[2]), "=r"(r[3]) : "r"(addr));
}
__device__ __forceinline__ void lds64(uint32_t* r, uint32_t addr) {
    asm volatile("ld.shared.v2.b32 {%0,%1}, [%2];"
                 : "=r"(r[0]), "=r"(r[1]) : "r"(addr));
}

__device__ __forceinline__ void mma_tf32(float* d, const uint32_t* a, const uint32_t* b) {
    asm volatile(
        "mma.sync.aligned.m16n8k8.row.col.f32.tf32.tf32.f32 "
        "{%0,%1,%2,%3}, {%4,%5,%6,%7}, {%8,%9}, {%0,%1,%2,%3};"
        : "+f"(d[0]), "+f"(d[1]), "+f"(d[2]), "+f"(d[3])
        : "r"(a[0]), "r"(a[1]), "r"(a[2]), "r"(a[3]), "r"(b[0]), "r"(b[1]));
}

// ---------------- coalesced pre-pass: smem-staged 64x64 tile transform ----------
// Blocks [0,8192): x -> g_A.  Blocks [8192,16384): w -> g_W.
// Loads: warp = 2 contiguous rows (512B). Writes: warp = 512B contiguous chunk.
// Output bytes identical to the R4/R5 prep (verified per-index vs fragment spec).
__global__ void __launch_bounds__(256) prep_kernel(const float* __restrict__ x,
                                                   const float* __restrict__ w) {
    __shared__ float s[64 * 68];                 // 64 rows, pad to 68 floats
    const int tid = threadIdx.x;
    const bool isA = blockIdx.x < 8192;
    const int bi = isA ? blockIdx.x : blockIdx.x - 8192;
    const int rowbase = (bi >> 5) * 64;
    const int colbase = (bi & 31) * 64;
    const float* src = (isA ? x : w) + (size_t)rowbase * NIN + colbase;

    // ---- load phase: 64x64 fp32, fully coalesced ----
    #pragma unroll
    for (int it = 0; it < 4; it++) {
        int L = tid + it * 256;                  // 0..1023
        int row = L >> 4, ch = L & 15;
        float4 v = *(const float4*)(src + (size_t)row * NIN + ch * 4);
        *(float4*)(&s[row * 68 + ch * 4]) = v;
    }
    __syncthreads();

    const int lane = tid & 31;
    const int wrp  = tid >> 5;                   // 0..7 == local kc unit
    if (isA) {
        const int b   = rowbase >> 7;
        const int mtb = (rowbase >> 4) & 7;      // 0 or 4
        const int kc  = (colbase >> 3) + wrp;
        const int lrg = lane >> 2, q = lane & 3;
        const int c   = wrp * 8 + q;
        #pragma unroll
        for (int r = 0; r < 4; r++) {            // local mtile
            const int r0 = r * 16 + lrg;
            float4 o;
            o.x = tf32r(s[r0 * 68 + c]);         // (row,   col)
            o.y = tf32r(s[(r0 + 8) * 68 + c]);   // (row+8, col)
            o.z = tf32r(s[r0 * 68 + c + 4]);     // (row,   col+4)
            o.w = tf32r(s[(r0 + 8) * 68 + c + 4]);
            *(float4*)(g_A + (((size_t)b * 256 + kc) * 8 + (mtb + r)) * 128
                       + lane * 4) = o;
        }
    } else {
        const int nb  = rowbase >> 8;
        const int ntb = (rowbase >> 3) & 31;     // 0,8,16,24
        const int kc  = (colbase >> 3) + wrp;
        const int l2  = lane & 15;
        const int hw  = lane >> 4;
        const int ln  = l2 >> 1;
        const int d0  = (l2 & 1) * 4;
        #pragma unroll
        for (int r = 0; r < 4; r++) {
            const int ntL = r * 2 + hw;          // local ntile 0..7
            const int row = ntL * 8 + ln;
            const float* sr = &s[row * 68 + wrp * 8];
            float4 o;                            // col = ((d0+m)>>1) + 4*((d0+m)&1)
            o.x = tf32r(sr[((d0 + 0) >> 1) + 4 * ((d0 + 0) & 1)]);
            o.y = tf32r(sr[((d0 + 1) >> 1) + 4 * ((d0 + 1) & 1)]);
            o.z = tf32r(sr[((d0 + 2) >> 1) + 4 * ((d0 + 2) & 1)]);
            o.w = tf32r(sr[((d0 + 3) >> 1) + 4 * ((d0 + 3) & 1)]);
            *(float4*)(g_W + (((size_t)nb * 256 + kc) * 32 + (ntb + ntL)) * 64
                       + l2 * 4) = o;
        }
    }
}

// ---------------- main grouped GEMM: R4-identical pipeline, flattened grid ------
__global__ void __launch_bounds__(NTHREADS, 1) gemm_kernel(
        const float* __restrict__ bias,
        const int*   __restrict__ tpe,
        float*       __restrict__ out) {
    extern __shared__ __align__(16) char smem[];

    const int nt = blockIdx.x;
    const int ti = blockIdx.y;                   // flattened active m-tile index

    int e = -1, mt = 0, start = 0, mycnt = 0;
    {
        int acc = 0, sacc = 0;
        #pragma unroll
        for (int i = 0; i < NE; i++) {
            int cc = __ldg(tpe + i);
            int tiles = (cc + BM - 1) >> 7;
            if (e < 0 && ti < acc + tiles) { e = i; mt = ti - acc; start = sacc; mycnt = cc; }
            acc += tiles; sacc += cc;
        }
    }
    if (e < 0) return;                           // beyond last active tile

    const int tid  = threadIdx.x;
    const int b    = (start >> 7) + mt;
    const int nb   = e * 8 + nt;
    const int m0   = start + mt * BM;

    const uint32_t sb     = smem_u32(smem);
    const uint32_t fullb  = sb;                  // STAGES x 8B
    const uint32_t emptyb = sb + 64;             // STAGES x 8B
    const uint32_t dbase  = sb + SMEM_CTRL;

    const float* Ab = g_A + (size_t)b  * 256 * 1024;
    const float* Bb = g_W + (size_t)nb * 256 * 2048;

    if (tid == 0) {
        #pragma unroll
        for (int s = 0; s < STAGES; s++) {
            MBAR_INIT(fullb + s * 8, 64);
            MBAR_INIT(emptyb + s * 8, 256);
        }
    }
    __syncthreads();

    if (tid >= 256) {
        // ================= producer warps (2 warps, 64 threads) =================
        const int ptid = tid - 256;
        #pragma unroll 1
        for (int k = 0; k < KITERS; k++) {
            const int s = k & (STAGES - 1);
            if (k >= STAGES) MBAR_WAIT(emptyb + s * 8, ((k >> 2) - 1) & 1);
            const float* As = Ab + (size_t)k * 4096;
            const float* Bs = Bb + (size_t)k * 8192;
            const uint32_t dA = dbase + s * STAGE_BYTES;
            const uint32_t dB = dA + A_STAGE_BYTES;
            #pragma unroll
            for (int i = 0; i < 16; i++)
                cp16(dA + (ptid + i * 64) * 16, As + (ptid + i * 64) * 4);
            #pragma unroll
            for (int i = 0; i < 32; i++)
                cp16(dB + (ptid + i * 64) * 16, Bs + (ptid + i * 64) * 4);
            CP_MBAR_ARRIVE(fullb + s * 8);
        }
    } else {
        // ================= compute warps (8 warps, 256 threads) =================
        const int lane = tid & 31;
        const int wid  = tid >> 5;
        const int wm   = wid & 1;
        const int wn   = wid >> 1;

        float acc[4][8][4];
        #pragma unroll
        for (int i = 0; i < 4; i++)
            #pragma unroll
            for (int j = 0; j < 8; j++)
                #pragma unroll
                for (int q = 0; q < 4; q++) acc[i][j][q] = 0.0f;

        #pragma unroll 1
        for (int k = 0; k < KITERS; k++) {
            const int s = k & (STAGES - 1);
            MBAR_WAIT(fullb + s * 8, (k >> 2) & 1);
            const uint32_t aBase = dbase + s * STAGE_BYTES;
            const uint32_t bBase = aBase + A_STAGE_BYTES;
            #pragma unroll
            for (int kcl = 0; kcl < 4; kcl++) {
                uint32_t af[4][4], bf[8][2];
                #pragma unroll
                for (int i = 0; i < 4; i++)
                    lds128(af[i], aBase + ((kcl * 8 + wm * 4 + i) * 128 + lane * 4) * 4);
                #pragma unroll
                for (int j = 0; j < 8; j++)
                    lds64(bf[j], bBase + ((kcl * 32 + wn * 8 + j) * 64 + lane * 2) * 4);
                #pragma unroll
                for (int i = 0; i < 4; i++)
                    #pragma unroll
                    for (int j = 0; j < 8; j++)
                        mma_tf32(acc[i][j], af[i], bf[j]);
            }
            MBAR_ARRIVE(emptyb + s * 8);
        }

        // ---- epilogue: bias add + fp32 store ----
        const int ncol0 = nt * BN + wn * 64;
        const float* bptr = bias + (size_t)e * NOUT + ncol0;
        #pragma unroll
        for (int j = 0; j < 8; j++) {
            const int cb = j * 8 + (lane & 3) * 2;
            const float bx = __ldg(bptr + cb);
            const float by = __ldg(bptr + cb + 1);
            #pragma unroll
            for (int i = 0; i < 4; i++) {
                const int r0 = wm * 64 + i * 16 + (lane >> 2);
                if (mt * BM + r0 < mycnt) {
                    float2 v = make_float2(acc[i][j][0] + bx, acc[i][j][1] + by);
                    *(float2*)(out + (size_t)(m0 + r0) * NOUT + ncol0 + cb) = v;
                }
                if (mt * BM + r0 + 8 < mycnt) {
                    float2 v = make_float2(acc[i][j][2] + bx, acc[i][j][3] + by);
                    *(float2*)(out + (size_t)(m0 + r0 + 8) * NOUT + ncol0 + cb) = v;
                }
            }
        }
    }
}

// ---------------- host launch ----------------
extern "C" void kernel_launch(void* const* d_in, const int* in_sizes, int n_in,
                              void* d_out, int out_size) {
    const float* x    = (const float*)d_in[0];
    const float* w    = (const float*)d_in[1];
    const float* bias = (const float*)d_in[2];
    const int*   tpe  = (const int*)d_in[3];
    float*       out  = (float*)d_out;

    prep_kernel<<<16384, 256>>>(x, w);          // coalesced A+W transform

    cudaFuncSetAttribute(gemm_kernel,
                         cudaFuncAttributeMaxDynamicSharedMemorySize, SMEM_TOTAL);
    dim3 grid(NOUT / BN, MAXTILES);             // (8, 136) flattened active tiles
    gemm_kernel<<<grid, NTHREADS, SMEM_TOTAL>>>(bias, tpe, out);
}